// round 14
// baseline (speedup 1.0000x reference)
#include <cuda_runtime.h>
#include <cuda_fp16.h>
#include <cstdint>
#include <math.h>

#define NT 16384
#define HH 2048
#define NE 64
#define NB 4
#define NS 4096
#define TM 64           // tokens per CTA
#define KT 64           // K elems per tile
#define NTILES (HH/KT)  // 32
#define THREADS 256
#define SMEM_BYTES 17152
#define TAU 2e-3f
#define MAXFIX 8192

// persistent scratch (allocation-free rule: __device__ globals)
__device__ float g_ssum[NB * NE];
__device__ int   g_cnt[NB * NE];
__device__ uint4 g_wfrag[4 * 128 * 32];   // [wn][kstep][lane] B fragments (fp16x2 packed)
__device__ int   g_nfix;
__device__ int   g_tick;
__device__ int   g_fix[MAXFIX];
__device__ float g_lg[MAXFIX * NE];       // stashed approx logits for flagged tokens

// ---------------- helpers ----------------
__device__ __forceinline__ uint32_t smem_u32(const void* p) {
    uint32_t a;
    asm("{ .reg .u64 t; cvta.to.shared.u64 t, %1; cvt.u32.u64 %0, t; }" : "=r"(a) : "l"(p));
    return a;
}
// pack two fp32 -> fp16x2 (lo arg -> bits[15:0], hi arg -> bits[31:16])
__device__ __forceinline__ uint32_t pack2h(float lo, float hi) {
    uint32_t r;
    asm("cvt.rn.f16x2.f32 %0, %1, %2;" : "=r"(r) : "f"(hi), "f"(lo));
    return r;
}
__device__ __forceinline__ void ldsm4(uint32_t* r, uint32_t addr) {
    asm volatile("ldmatrix.sync.aligned.m8n8.x4.shared.b16 {%0,%1,%2,%3}, [%4];"
                 : "=r"(r[0]), "=r"(r[1]), "=r"(r[2]), "=r"(r[3]) : "r"(addr));
}
__device__ __forceinline__ void mma16816(float* d, const uint32_t* a, const uint32_t* b) {
    asm volatile("mma.sync.aligned.m16n8k16.row.col.f32.f16.f16.f32 "
                 "{%0,%1,%2,%3}, {%4,%5,%6,%7}, {%8,%9}, {%0,%1,%2,%3};"
                 : "+f"(d[0]), "+f"(d[1]), "+f"(d[2]), "+f"(d[3])
                 : "r"(a[0]), "r"(a[1]), "r"(a[2]), "r"(a[3]), "r"(b[0]), "r"(b[1]));
}

// ---------------- W fragment-pack kernel (+ counter resets) ----------------
__global__ __launch_bounds__(256) void k_wconv(const float* __restrict__ W) {
    int i = blockIdx.x * 256 + threadIdx.x;    // 0..16383
    if (i == 0) { g_nfix = 0; g_tick = 0; }
    int wn = i >> 12;            // 0..3 (warp column)
    int ks = (i >> 5) & 127;     // global k-step (k16)
    int L  = i & 31;             // lane
    int e0 = wn * 16 + (L >> 2);
    int k0 = ks * 16 + (L & 3) * 2;
    const float* w0 = W + (size_t)e0 * HH + k0;
    const float* w8 = W + (size_t)(e0 + 8) * HH + k0;
    uint4 v;
    v.x = pack2h(w0[0], w0[1]);
    v.y = pack2h(w0[8], w0[9]);
    v.z = pack2h(w8[0], w8[1]);
    v.w = pack2h(w8[8], w8[9]);
    g_wfrag[i] = v;
}

// ---------------- main gate kernel (fp16 HMMA, B direct-from-L2 fragments) ----------------
__global__ __launch_bounds__(THREADS, 3)
void k_gate(const float* __restrict__ X, float* __restrict__ out, int wbase) {
    extern __shared__ char smem[];
    const int tid  = threadIdx.x;
    const int wid  = tid >> 5;
    const int lane = tid & 31;
    const uint32_t sb = smem_u32(smem);
    const int tokBase = blockIdx.x * TM;

    int* scnt = (int*)(smem + 16896);
    if (tid < NE) scnt[tid] = 0;

    // smem: A(s) = sb + s*8192 (64 rows x 128B fp16, swizzled); later Lg[64][66]
    const uint32_t HA = sb;

    // ---- X gmem addressing: row = tid>>2 (0..63), q = tid&3, quads q+4p ----
    const int xrow = tid >> 2;
    const int xq   = tid & 3;
    const float* xp = X + (size_t)(tokBase + xrow) * HH + xq * 4;

    // ---- STS swizzled offsets ----
    uint32_t xoff[4];
#pragma unroll
    for (int p = 0; p < 4; p++) {
        uint32_t off = (uint32_t)xrow * 128u + (uint32_t)(xq + 4 * p) * 8u;
        xoff[p] = off ^ ((off >> 3) & 0x70);
    }

    // ---- LDSM/warp addressing: warp (wm, wn): rows wm*32..+31, cols wn*16..+15 ----
    const int wm = wid & 1;
    const int wn = wid >> 1;
    const uint32_t xorK  = (uint32_t)(lane & 7);
    const uint32_t kselA = (uint32_t)(lane >> 4);
    uint32_t rowA[2];
#pragma unroll
    for (int mt = 0; mt < 2; mt++)
        rowA[mt] = (uint32_t)(wm * 32 + mt * 16 + (lane & 15)) * 128u;

    // B fragment base index for this warp
    const uint4* wf = g_wfrag + (size_t)wn * 128 * 32 + lane;

    float acc[2][2][4];
#pragma unroll
    for (int mt = 0; mt < 2; mt++)
#pragma unroll
        for (int q = 0; q < 2; q++)
#pragma unroll
            for (int e = 0; e < 4; e++) acc[mt][q][e] = 0.0f;

    // ---- prologue: X(0) into regs ----
    float4 xv[4];
#pragma unroll
    for (int p = 0; p < 4; p++) xv[p] = *(const float4*)(xp + p * 16);

    for (int t = 0; t < NTILES; t++) {
        const uint32_t A = HA + (uint32_t)(t & 1) * 8192u;

        // STS X(t) (convert fp32->fp16)
#pragma unroll
        for (int p = 0; p < 4; p++) {
            uint32_t xa = pack2h(xv[p].x, xv[p].y);
            uint32_t xb = pack2h(xv[p].z, xv[p].w);
            asm volatile("st.shared.v2.u32 [%0], {%1,%2};" :: "r"(A + xoff[p]), "r"(xa), "r"(xb));
        }

        // B fragments for tile t (L2; issued before barrier to overlap wait)
        uint4 bfk[4];
#pragma unroll
        for (int ks = 0; ks < 4; ks++)
            bfk[ks] = wf[(t * 4 + ks) * 32];

        // prefetch X(t+1) into regs
        if (t + 1 < NTILES) {
            const int k0 = (t + 1) * KT;
#pragma unroll
            for (int p = 0; p < 4; p++) xv[p] = *(const float4*)(xp + k0 + p * 16);
        }

        __syncthreads();

        // ---- ldmatrix A + mma ----
#pragma unroll
        for (int ks = 0; ks < 4; ks++) {
            const uint32_t kA = (uint32_t)(2 * ks) + kselA;
            uint32_t af[2][4];
            ldsm4(af[0], A + rowA[0] + ((kA ^ xorK) << 4));
            ldsm4(af[1], A + rowA[1] + ((kA ^ xorK) << 4));
            const uint32_t* bf = (const uint32_t*)&bfk[ks];
#pragma unroll
            for (int mt = 0; mt < 2; mt++) {
                mma16816(acc[mt][0], af[mt], bf + 0);
                mma16816(acc[mt][1], af[mt], bf + 2);
            }
        }
    }

    __syncthreads();   // A buffers free; reuse as logits

    // ---- accumulators -> logits smem [64][66] ----
    float* Lg = (float*)smem;
    {
        const int g  = lane >> 2;
        const int tg = lane & 3;
#pragma unroll
        for (int mt = 0; mt < 2; mt++)
#pragma unroll
            for (int q = 0; q < 2; q++) {
                int m0 = wm * 32 + mt * 16 + g;
                int c  = wn * 16 + q * 8 + tg * 2;
                Lg[m0 * 66 + c]           = acc[mt][q][0];
                Lg[m0 * 66 + c + 1]       = acc[mt][q][1];
                Lg[(m0 + 8) * 66 + c]     = acc[mt][q][2];
                Lg[(m0 + 8) * 66 + c + 1] = acc[mt][q][3];
            }
    }
    __syncthreads();

    // ---- per-token softmax / top-2 (+ near-tie flagging with logit stash) ----
    if (tid < TM) {
        float v[64];
#pragma unroll
        for (int e = 0; e < NE; e++) v[e] = Lg[tid * 66 + e];

        float m = -1e30f;
#pragma unroll
        for (int e = 0; e < NE; e++) m = fmaxf(m, v[e]);

        float Z = 0.0f, b1 = -1e30f, b2 = -1e30f, b3 = -1e30f;
        int i1 = 0, i2 = 0;
#pragma unroll
        for (int e = 0; e < NE; e++) {
            float x = v[e];
            float ex = __expf(x - m);
            v[e] = ex;
            Z += ex;
            if (x > b1)      { b3 = b2; b2 = b1; i2 = i1; b1 = x; i1 = e; }
            else if (x > b2) { b3 = b2; b2 = x;  i2 = e; }
            else if (x > b3) { b3 = x; }
        }
        float invZ = 1.0f / Z;
        float s1 = v[i1] * invZ;
        float s2 = v[i2] * invZ;
        float den = s1 + s2 + 1e-20f;

        int gt = tokBase + tid;
        out[gt * 2 + 0] = (float)i1;
        out[gt * 2 + 1] = (float)i2;
        out[wbase + gt * 2 + 0] = s1 / den;
        out[wbase + gt * 2 + 1] = s2 / den;

        if ((b1 - b2 < TAU) || (b2 - b3 < TAU)) {
            int slot = atomicAdd(&g_nfix, 1);
            if (slot < MAXFIX) {
                g_fix[slot] = gt;
                for (int e = 0; e < NE; e++) g_lg[slot * NE + e] = Lg[tid * 66 + e];
            }
        }

        atomicAdd(&scnt[i1], 1);
        atomicAdd(&scnt[i2], 1);

#pragma unroll
        for (int e = 0; e < NE; e++) Lg[tid * 66 + e] = v[e] * invZ;
    }
    __syncthreads();

    if (tid < NE) {
        float ssum = 0.0f;
        for (int r = 0; r < TM; r++) ssum += Lg[r * 66 + tid];
        const int b = tokBase >> 12;
        atomicAdd(&g_ssum[b * NE + tid], ssum);
        int c = scnt[tid];
        if (c) atomicAdd(&g_cnt[b * NE + tid], c);
    }
}

// ---------------- candidate-based exact fixup + fused aux loss ----------------
__global__ __launch_bounds__(256) void k_fixup(const float* __restrict__ X,
                                               const float* __restrict__ W,
                                               float* __restrict__ out, int wbase,
                                               int aux_idx) {
    __shared__ float la[64];
    __shared__ int   cand[8];
    __shared__ int   ccnt;
    __shared__ int   amLast;
    __shared__ float red[NB * NE];
    int n = g_nfix;
    if (n > MAXFIX) n = MAXFIX;
    const int tid  = threadIdx.x;
    const int w    = tid >> 5;
    const int lane = tid & 31;

    for (int s = blockIdx.x; s < n; s += gridDim.x) {
        const int gt = g_fix[s];
        if (tid < 64) la[tid] = g_lg[s * NE + tid];
        __syncthreads();

        if (tid == 0) {
            float b1 = -1e30f, b2 = -1e30f;
            for (int q = 0; q < 64; q++) {
                float x = la[q];
                if (x > b1) { b2 = b1; b1 = x; }
                else if (x > b2) b2 = x;
            }
            const float thr = b2 - TAU;
            unsigned long long used = 0;
            int c = 0;
            for (int it = 0; it < 8; it++) {
                float bm = -1e30f; int bi = -1;
                for (int q = 0; q < 64; q++)
                    if (!((used >> q) & 1ull) && la[q] > bm) { bm = la[q]; bi = q; }
                if (bm < thr) break;
                used |= 1ull << bi;
                cand[c++] = bi;
            }
            ccnt = c;
        }
        __syncthreads();

        if (w < ccnt) {
            const int e = cand[w];
            const float4* xr = (const float4*)(X + (size_t)gt * HH);
            const float4* wr = (const float4*)(W + (size_t)e * HH);
            float a0 = 0.f, a1 = 0.f;
#pragma unroll
            for (int i = 0; i < 16; i += 2) {
                float4 x0 = xr[lane + 32 * i];
                float4 w0 = wr[lane + 32 * i];
                float4 x1 = xr[lane + 32 * (i + 1)];
                float4 w1 = wr[lane + 32 * (i + 1)];
                a0 = fmaf(x0.x, w0.x, a0); a0 = fmaf(x0.y, w0.y, a0);
                a0 = fmaf(x0.z, w0.z, a0); a0 = fmaf(x0.w, w0.w, a0);
                a1 = fmaf(x1.x, w1.x, a1); a1 = fmaf(x1.y, w1.y, a1);
                a1 = fmaf(x1.z, w1.z, a1); a1 = fmaf(x1.w, w1.w, a1);
            }
            float a = a0 + a1;
#pragma unroll
            for (int off = 16; off > 0; off >>= 1)
                a += __shfl_xor_sync(0xffffffffu, a, off);
            if (lane == 0) la[e] = a;
        }
        __syncthreads();

        if (tid == 0) {
            float m = -1e30f;
            for (int q = 0; q < 64; q++) m = fmaxf(m, la[q]);
            float Z = 0.f, b1 = -1e30f, b2 = -1e30f;
            int i1 = 0, i2 = 0;
            for (int q = 0; q < 64; q++) {
                float x = la[q];
                Z += __expf(x - m);
                if (x > b1)      { b2 = b1; i2 = i1; b1 = x; i1 = q; }
                else if (x > b2) { b2 = x;  i2 = q; }
            }
            float s1 = __expf(b1 - m) / Z;
            float s2 = __expf(b2 - m) / Z;
            float den = s1 + s2 + 1e-20f;

            int o1 = (int)out[gt * 2 + 0];
            int o2 = (int)out[gt * 2 + 1];
            const int b = gt >> 12;
            if (o1 != i1) { atomicAdd(&g_cnt[b * NE + o1], -1); atomicAdd(&g_cnt[b * NE + i1], 1); }
            if (o2 != i2) { atomicAdd(&g_cnt[b * NE + o2], -1); atomicAdd(&g_cnt[b * NE + i2], 1); }

            out[gt * 2 + 0] = (float)i1;
            out[gt * 2 + 1] = (float)i2;
            out[wbase + gt * 2 + 0] = s1 / den;
            out[wbase + gt * 2 + 1] = s2 / den;
        }
        __syncthreads();
    }

    // ---- fused aux loss: last block to finish computes it ----
    __threadfence();
    if (tid == 0) amLast = (atomicAdd(&g_tick, 1) == (int)gridDim.x - 1);
    __syncthreads();
    if (amLast) {
        float v = (float)g_cnt[tid] * ((float)NE / (float)(NS * 2)) * (g_ssum[tid] / (float)NS);
        red[tid] = v;
        g_cnt[tid] = 0;       // reset scratch for next graph replay
        g_ssum[tid] = 0.0f;
        if (tid == 0) { g_tick = 0; g_nfix = 0; }
        __syncthreads();
        for (int s = 128; s > 0; s >>= 1) {
            if (tid < s) red[tid] += red[tid + s];
            __syncthreads();
        }
        if (tid == 0) out[aux_idx] = red[0] / (float)NB * 0.1f;
    }
}

extern "C" void kernel_launch(void* const* d_in, const int* in_sizes, int n_in,
                              void* d_out, int out_size) {
    const float* X = (const float*)d_in[0];   // [4,4096,2048] fp32
    const float* W = (const float*)d_in[1];   // [64,2048] fp32
    float* out = (float*)d_out;
    const int wbase = (out_size - 1) / 2;     // 32768

    cudaFuncSetAttribute(k_gate, cudaFuncAttributeMaxDynamicSharedMemorySize, SMEM_BYTES);

    k_wconv<<<64, 256>>>(W);
    k_gate<<<NT / TM, THREADS, SMEM_BYTES>>>(X, out, wbase);
    k_fixup<<<296, 256>>>(X, W, out, wbase, out_size - 1);
}

// round 15
// speedup vs baseline: 1.0058x; 1.0058x over previous
#include <cuda_runtime.h>
#include <cuda_fp16.h>
#include <cstdint>
#include <math.h>

#define NT 16384
#define HH 2048
#define NE 64
#define NB 4
#define NS 4096
#define TM 64           // tokens per CTA
#define KT 64           // K elems per tile
#define NTILES (HH/KT)  // 32
#define THREADS 256
#define STAGE 17408     // 64 rows x 272B (fp32 tile, padded)
#define SMEM_BYTES 68864
#define TAU 2e-3f
#define MAXFIX 8192

// persistent scratch (allocation-free rule: __device__ globals)
__device__ float g_ssum[NB * NE];
__device__ int   g_cnt[NB * NE];
__device__ uint4 g_wfrag[4 * 128 * 32];   // [wn][kstep][lane] B fragments (fp16x2 packed)
__device__ int   g_nfix;
__device__ int   g_tick;
__device__ int   g_fix[MAXFIX];
__device__ float g_lg[MAXFIX * NE];       // stashed approx logits for flagged tokens

// ---------------- helpers ----------------
__device__ __forceinline__ uint32_t smem_u32(const void* p) {
    uint32_t a;
    asm("{ .reg .u64 t; cvta.to.shared.u64 t, %1; cvt.u32.u64 %0, t; }" : "=r"(a) : "l"(p));
    return a;
}
// pack two fp32 -> fp16x2 (lo arg -> bits[15:0], hi arg -> bits[31:16])
__device__ __forceinline__ uint32_t pack2h(float lo, float hi) {
    uint32_t r;
    asm("cvt.rn.f16x2.f32 %0, %1, %2;" : "=r"(r) : "f"(hi), "f"(lo));
    return r;
}
__device__ __forceinline__ void ldsm4(uint32_t* r, uint32_t addr) {
    asm volatile("ldmatrix.sync.aligned.m8n8.x4.shared.b16 {%0,%1,%2,%3}, [%4];"
                 : "=r"(r[0]), "=r"(r[1]), "=r"(r[2]), "=r"(r[3]) : "r"(addr));
}
__device__ __forceinline__ void mma16816(float* d, const uint32_t* a, const uint32_t* b) {
    asm volatile("mma.sync.aligned.m16n8k16.row.col.f32.f16.f16.f32 "
                 "{%0,%1,%2,%3}, {%4,%5,%6,%7}, {%8,%9}, {%0,%1,%2,%3};"
                 : "+f"(d[0]), "+f"(d[1]), "+f"(d[2]), "+f"(d[3])
                 : "r"(a[0]), "r"(a[1]), "r"(a[2]), "r"(a[3]), "r"(b[0]), "r"(b[1]));
}
__device__ __forceinline__ void cp16(uint32_t smem_dst, const void* gmem_src) {
    asm volatile("cp.async.cg.shared.global [%0], [%1], 16;"
                 :: "r"(smem_dst), "l"(gmem_src) : "memory");
}
#define CP_COMMIT() asm volatile("cp.async.commit_group;" ::: "memory")
#define CP_WAIT(n)  asm volatile("cp.async.wait_group %0;" :: "n"(n) : "memory")

// ---------------- W fragment-pack kernel (+ counter resets) ----------------
__global__ __launch_bounds__(256) void k_wconv(const float* __restrict__ W) {
    int i = blockIdx.x * 256 + threadIdx.x;    // 0..16383
    if (i == 0) { g_nfix = 0; g_tick = 0; }
    int wn = i >> 12;            // 0..3 (warp column)
    int ks = (i >> 5) & 127;     // global k-step (k16)
    int L  = i & 31;             // lane
    int e0 = wn * 16 + (L >> 2);
    int k0 = ks * 16 + (L & 3) * 2;
    const float* w0 = W + (size_t)e0 * HH + k0;
    const float* w8 = W + (size_t)(e0 + 8) * HH + k0;
    uint4 v;
    v.x = pack2h(w0[0], w0[1]);
    v.y = pack2h(w0[8], w0[9]);
    v.z = pack2h(w8[0], w8[1]);
    v.w = pack2h(w8[8], w8[9]);
    g_wfrag[i] = v;
}

// ---------------- main gate kernel (fp16 HMMA, 3-stage cp.async X pipeline) ----------------
__global__ __launch_bounds__(THREADS, 3)
void k_gate(const float* __restrict__ X, float* __restrict__ out, int wbase) {
    extern __shared__ char smem[];
    const int tid  = threadIdx.x;
    const int wid  = tid >> 5;
    const int lane = tid & 31;
    const uint32_t sb = smem_u32(smem);
    const int tokBase = blockIdx.x * TM;

    int* scnt = (int*)(smem + 3 * STAGE + 16384);
    if (tid < NE) scnt[tid] = 0;

    // smem: X stages [3][64 rows][272B fp32] @ sb
    //       A(s) fp16 swizzled [64][128B] @ sb + 3*STAGE + s*8192
    const uint32_t SX = sb;
    const uint32_t HA = sb + 3u * STAGE;

    // ---- thread mapping: row = tid>>2 (0..63), q = tid&3; chunks c = q+4p ----
    const int row = tid >> 2;
    const int q   = tid & 3;
    const char* xg = (const char*)X + ((size_t)(tokBase + row) * HH + q * 4) * 4;
    const uint32_t xsoff = (uint32_t)row * 272u + (uint32_t)q * 16u;   // stage-local

    // fp16 A swizzled STS offsets
    uint32_t xoff[4];
#pragma unroll
    for (int p = 0; p < 4; p++) {
        uint32_t off = (uint32_t)row * 128u + (uint32_t)(q + 4 * p) * 8u;
        xoff[p] = off ^ ((off >> 3) & 0x70);
    }

    // ---- LDSM/warp addressing: warp (wm, wn): rows wm*32..+31, cols wn*16..+15 ----
    const int wm = wid & 1;
    const int wn = wid >> 1;
    const uint32_t xorK  = (uint32_t)(lane & 7);
    const uint32_t kselA = (uint32_t)(lane >> 4);
    uint32_t rowA[2];
#pragma unroll
    for (int mt = 0; mt < 2; mt++)
        rowA[mt] = (uint32_t)(wm * 32 + mt * 16 + (lane & 15)) * 128u;

    const uint4* wf = g_wfrag + (size_t)wn * 128 * 32 + lane;

    float acc[2][2][4];
#pragma unroll
    for (int mt = 0; mt < 2; mt++)
#pragma unroll
        for (int qq = 0; qq < 2; qq++)
#pragma unroll
            for (int e = 0; e < 4; e++) acc[mt][qq][e] = 0.0f;

    // ---- prologue: stages 0,1,2 in flight ----
#pragma unroll
    for (int t = 0; t < 3; t++) {
        const uint32_t dst = SX + (uint32_t)t * STAGE + xsoff;
        const char* src = xg + t * 256;
#pragma unroll
        for (int p = 0; p < 4; p++) cp16(dst + p * 64u, src + p * 64);
        CP_COMMIT();
    }

    int stg = 0;
    for (int t = 0; t < NTILES; t++) {
        const uint32_t A = HA + (uint32_t)(t & 1) * 8192u;

        // B fragments for tile t (L2; overlap with wait)
        uint4 bfk[4];
#pragma unroll
        for (int ks = 0; ks < 4; ks++)
            bfk[ks] = wf[(t * 4 + ks) * 32];

        CP_WAIT(2);   // X(t) landed (own-thread chunks; no barrier needed)

        // convert X(t) fp32 -> fp16 into A(t&1)
        const uint32_t xs = SX + (uint32_t)stg * STAGE + xsoff;
#pragma unroll
        for (int p = 0; p < 4; p++) {
            float v0, v1, v2, v3;
            asm volatile("ld.shared.v4.f32 {%0,%1,%2,%3}, [%4];"
                         : "=f"(v0), "=f"(v1), "=f"(v2), "=f"(v3) : "r"(xs + p * 64u));
            uint32_t ha = pack2h(v0, v1);
            uint32_t hb = pack2h(v2, v3);
            asm volatile("st.shared.v2.u32 [%0], {%1,%2};" :: "r"(A + xoff[p]), "r"(ha), "r"(hb));
        }

        // issue X(t+3) into the stage just freed (write-after-own-read: safe)
        if (t + 3 < NTILES) {
            const uint32_t dst = SX + (uint32_t)stg * STAGE + xsoff;
            const char* src = xg + (t + 3) * 256;
#pragma unroll
            for (int p = 0; p < 4; p++) cp16(dst + p * 64u, src + p * 64);
            CP_COMMIT();
        } else {
            CP_COMMIT();   // empty group keeps the wait count honest
        }
        stg = (stg == 2) ? 0 : stg + 1;

        __syncthreads();

        // ---- ldmatrix A + mma ----
#pragma unroll
        for (int ks = 0; ks < 4; ks++) {
            const uint32_t kA = (uint32_t)(2 * ks) + kselA;
            uint32_t af[2][4];
            ldsm4(af[0], A + rowA[0] + ((kA ^ xorK) << 4));
            ldsm4(af[1], A + rowA[1] + ((kA ^ xorK) << 4));
            const uint32_t* bf = (const uint32_t*)&bfk[ks];
#pragma unroll
            for (int mt = 0; mt < 2; mt++) {
                mma16816(acc[mt][0], af[mt], bf + 0);
                mma16816(acc[mt][1], af[mt], bf + 2);
            }
        }
    }

    __syncthreads();   // buffers free; reuse as logits

    // ---- accumulators -> logits smem [64][66] ----
    float* Lg = (float*)smem;
    {
        const int g  = lane >> 2;
        const int tg = lane & 3;
#pragma unroll
        for (int mt = 0; mt < 2; mt++)
#pragma unroll
            for (int qq = 0; qq < 2; qq++) {
                int m0 = wm * 32 + mt * 16 + g;
                int c  = wn * 16 + qq * 8 + tg * 2;
                Lg[m0 * 66 + c]           = acc[mt][qq][0];
                Lg[m0 * 66 + c + 1]       = acc[mt][qq][1];
                Lg[(m0 + 8) * 66 + c]     = acc[mt][qq][2];
                Lg[(m0 + 8) * 66 + c + 1] = acc[mt][qq][3];
            }
    }
    __syncthreads();

    // ---- per-token softmax / top-2 (+ near-tie flagging with logit stash) ----
    if (tid < TM) {
        float v[64];
#pragma unroll
        for (int e = 0; e < NE; e++) v[e] = Lg[tid * 66 + e];

        float m = -1e30f;
#pragma unroll
        for (int e = 0; e < NE; e++) m = fmaxf(m, v[e]);

        float Z = 0.0f, b1 = -1e30f, b2 = -1e30f, b3 = -1e30f;
        int i1 = 0, i2 = 0;
#pragma unroll
        for (int e = 0; e < NE; e++) {
            float x = v[e];
            float ex = __expf(x - m);
            v[e] = ex;
            Z += ex;
            if (x > b1)      { b3 = b2; b2 = b1; i2 = i1; b1 = x; i1 = e; }
            else if (x > b2) { b3 = b2; b2 = x;  i2 = e; }
            else if (x > b3) { b3 = x; }
        }
        float invZ = 1.0f / Z;
        float s1 = v[i1] * invZ;
        float s2 = v[i2] * invZ;
        float den = s1 + s2 + 1e-20f;

        int gt = tokBase + tid;
        out[gt * 2 + 0] = (float)i1;
        out[gt * 2 + 1] = (float)i2;
        out[wbase + gt * 2 + 0] = s1 / den;
        out[wbase + gt * 2 + 1] = s2 / den;

        if ((b1 - b2 < TAU) || (b2 - b3 < TAU)) {
            int slot = atomicAdd(&g_nfix, 1);
            if (slot < MAXFIX) {
                g_fix[slot] = gt;
                for (int e = 0; e < NE; e++) g_lg[slot * NE + e] = Lg[tid * 66 + e];
            }
        }

        atomicAdd(&scnt[i1], 1);
        atomicAdd(&scnt[i2], 1);

#pragma unroll
        for (int e = 0; e < NE; e++) Lg[tid * 66 + e] = v[e] * invZ;
    }
    __syncthreads();

    if (tid < NE) {
        float ssum = 0.0f;
        for (int r = 0; r < TM; r++) ssum += Lg[r * 66 + tid];
        const int b = tokBase >> 12;
        atomicAdd(&g_ssum[b * NE + tid], ssum);
        int c = scnt[tid];
        if (c) atomicAdd(&g_cnt[b * NE + tid], c);
    }
}

// ---------------- candidate-based exact fixup + fused aux loss ----------------
__global__ __launch_bounds__(256) void k_fixup(const float* __restrict__ X,
                                               const float* __restrict__ W,
                                               float* __restrict__ out, int wbase,
                                               int aux_idx) {
    __shared__ float la[64];
    __shared__ int   cand[8];
    __shared__ int   ccnt;
    __shared__ int   amLast;
    __shared__ float red[NB * NE];
    int n = g_nfix;
    if (n > MAXFIX) n = MAXFIX;
    const int tid  = threadIdx.x;
    const int w    = tid >> 5;
    const int lane = tid & 31;

    for (int s = blockIdx.x; s < n; s += gridDim.x) {
        const int gt = g_fix[s];
        if (tid < 64) la[tid] = g_lg[s * NE + tid];
        __syncthreads();

        if (tid == 0) {
            float b1 = -1e30f, b2 = -1e30f;
            for (int qq = 0; qq < 64; qq++) {
                float x = la[qq];
                if (x > b1) { b2 = b1; b1 = x; }
                else if (x > b2) b2 = x;
            }
            const float thr = b2 - TAU;
            unsigned long long used = 0;
            int c = 0;
            for (int it = 0; it < 8; it++) {
                float bm = -1e30f; int bi = -1;
                for (int qq = 0; qq < 64; qq++)
                    if (!((used >> qq) & 1ull) && la[qq] > bm) { bm = la[qq]; bi = qq; }
                if (bm < thr) break;
                used |= 1ull << bi;
                cand[c++] = bi;
            }
            ccnt = c;
        }
        __syncthreads();

        if (w < ccnt) {
            const int e = cand[w];
            const float4* xr = (const float4*)(X + (size_t)gt * HH);
            const float4* wr = (const float4*)(W + (size_t)e * HH);
            float a0 = 0.f, a1 = 0.f;
#pragma unroll
            for (int i = 0; i < 16; i += 2) {
                float4 x0 = xr[lane + 32 * i];
                float4 w0 = wr[lane + 32 * i];
                float4 x1 = xr[lane + 32 * (i + 1)];
                float4 w1 = wr[lane + 32 * (i + 1)];
                a0 = fmaf(x0.x, w0.x, a0); a0 = fmaf(x0.y, w0.y, a0);
                a0 = fmaf(x0.z, w0.z, a0); a0 = fmaf(x0.w, w0.w, a0);
                a1 = fmaf(x1.x, w1.x, a1); a1 = fmaf(x1.y, w1.y, a1);
                a1 = fmaf(x1.z, w1.z, a1); a1 = fmaf(x1.w, w1.w, a1);
            }
            float a = a0 + a1;
#pragma unroll
            for (int off = 16; off > 0; off >>= 1)
                a += __shfl_xor_sync(0xffffffffu, a, off);
            if (lane == 0) la[e] = a;
        }
        __syncthreads();

        if (tid == 0) {
            float m = -1e30f;
            for (int qq = 0; qq < 64; qq++) m = fmaxf(m, la[qq]);
            float Z = 0.f, b1 = -1e30f, b2 = -1e30f;
            int i1 = 0, i2 = 0;
            for (int qq = 0; qq < 64; qq++) {
                float x = la[qq];
                Z += __expf(x - m);
                if (x > b1)      { b2 = b1; i2 = i1; b1 = x; i1 = qq; }
                else if (x > b2) { b2 = x;  i2 = qq; }
            }
            float s1 = __expf(b1 - m) / Z;
            float s2 = __expf(b2 - m) / Z;
            float den = s1 + s2 + 1e-20f;

            int o1 = (int)out[gt * 2 + 0];
            int o2 = (int)out[gt * 2 + 1];
            const int b = gt >> 12;
            if (o1 != i1) { atomicAdd(&g_cnt[b * NE + o1], -1); atomicAdd(&g_cnt[b * NE + i1], 1); }
            if (o2 != i2) { atomicAdd(&g_cnt[b * NE + o2], -1); atomicAdd(&g_cnt[b * NE + i2], 1); }

            out[gt * 2 + 0] = (float)i1;
            out[gt * 2 + 1] = (float)i2;
            out[wbase + gt * 2 + 0] = s1 / den;
            out[wbase + gt * 2 + 1] = s2 / den;
        }
        __syncthreads();
    }

    // ---- fused aux loss: last block to finish computes it ----
    __threadfence();
    if (tid == 0) amLast = (atomicAdd(&g_tick, 1) == (int)gridDim.x - 1);
    __syncthreads();
    if (amLast) {
        float v = (float)g_cnt[tid] * ((float)NE / (float)(NS * 2)) * (g_ssum[tid] / (float)NS);
        red[tid] = v;
        g_cnt[tid] = 0;       // reset scratch for next graph replay
        g_ssum[tid] = 0.0f;
        if (tid == 0) { g_tick = 0; g_nfix = 0; }
        __syncthreads();
        for (int s = 128; s > 0; s >>= 1) {
            if (tid < s) red[tid] += red[tid + s];
            __syncthreads();
        }
        if (tid == 0) out[aux_idx] = red[0] / (float)NB * 0.1f;
    }
}

extern "C" void kernel_launch(void* const* d_in, const int* in_sizes, int n_in,
                              void* d_out, int out_size) {
    const float* X = (const float*)d_in[0];   // [4,4096,2048] fp32
    const float* W = (const float*)d_in[1];   // [64,2048] fp32
    float* out = (float*)d_out;
    const int wbase = (out_size - 1) / 2;     // 32768

    cudaFuncSetAttribute(k_gate, cudaFuncAttributeMaxDynamicSharedMemorySize, SMEM_BYTES);

    k_wconv<<<64, 256>>>(W);
    k_gate<<<NT / TM, THREADS, SMEM_BYTES>>>(X, out, wbase);
    k_fixup<<<296, 256>>>(X, W, out, wbase, out_size - 1);
}

// round 16
// speedup vs baseline: 1.3587x; 1.3509x over previous
#include <cuda_runtime.h>
#include <cuda_fp16.h>
#include <cstdint>
#include <math.h>

#define NT 16384
#define HH 2048
#define NE 64
#define NB 4
#define NS 4096
#define TM 64           // tokens per CTA
#define KT 64           // K elems per tile
#define NTILES (HH/KT)  // 32
#define THREADS 256
#define SMEM_BYTES 33024
#define TAU 2e-3f
#define MAXFIX 8192

// persistent scratch (allocation-free rule: __device__ globals)
__device__ float    g_ssum[NB * NE];
__device__ int      g_cnt[NB * NE];
__device__ uint32_t g_wh[NE * HH / 2];   // fp16x2-packed W
__device__ int      g_nfix;
__device__ int      g_tick;
__device__ int      g_fix[MAXFIX];
__device__ float    g_lg[MAXFIX * NE];   // stashed approx logits for flagged tokens

// ---------------- helpers ----------------
__device__ __forceinline__ uint32_t smem_u32(const void* p) {
    uint32_t a;
    asm("{ .reg .u64 t; cvta.to.shared.u64 t, %1; cvt.u32.u64 %0, t; }" : "=r"(a) : "l"(p));
    return a;
}
__device__ __forceinline__ uint32_t pack2h(float lo, float hi) {
    uint32_t r;
    asm("cvt.rn.f16x2.f32 %0, %1, %2;" : "=r"(r) : "f"(hi), "f"(lo));
    return r;
}
__device__ __forceinline__ void ldsm4(uint32_t* r, uint32_t addr) {
    asm volatile("ldmatrix.sync.aligned.m8n8.x4.shared.b16 {%0,%1,%2,%3}, [%4];"
                 : "=r"(r[0]), "=r"(r[1]), "=r"(r[2]), "=r"(r[3]) : "r"(addr));
}
__device__ __forceinline__ void mma16816(float* d, const uint32_t* a, const uint32_t* b) {
    asm volatile("mma.sync.aligned.m16n8k16.row.col.f32.f16.f16.f32 "
                 "{%0,%1,%2,%3}, {%4,%5,%6,%7}, {%8,%9}, {%0,%1,%2,%3};"
                 : "+f"(d[0]), "+f"(d[1]), "+f"(d[2]), "+f"(d[3])
                 : "r"(a[0]), "r"(a[1]), "r"(a[2]), "r"(a[3]), "r"(b[0]), "r"(b[1]));
}
__device__ __forceinline__ void cp16(uint32_t smem_dst, const void* gmem_src) {
    asm volatile("cp.async.cg.shared.global [%0], [%1], 16;"
                 :: "r"(smem_dst), "l"(gmem_src) : "memory");
}
#define CP_COMMIT() asm volatile("cp.async.commit_group;" ::: "memory")
#define CP_WAIT(n)  asm volatile("cp.async.wait_group %0;" :: "n"(n) : "memory")

__device__ __forceinline__ float warp_max(float v) {
#pragma unroll
    for (int off = 16; off > 0; off >>= 1)
        v = fmaxf(v, __shfl_xor_sync(0xffffffffu, v, off));
    return v;
}
__device__ __forceinline__ float warp_sum(float v) {
#pragma unroll
    for (int off = 16; off > 0; off >>= 1)
        v += __shfl_xor_sync(0xffffffffu, v, off);
    return v;
}

// ---------------- W convert kernel (+ counter resets) ----------------
__global__ __launch_bounds__(256) void k_wconv(const float* __restrict__ W) {
    if (blockIdx.x == 0 && threadIdx.x == 0) { g_nfix = 0; g_tick = 0; }
    int i = (blockIdx.x * 256 + threadIdx.x) * 4;
    float4 v = *(const float4*)(W + i);
    ((uint2*)g_wh)[i >> 2] = make_uint2(pack2h(v.x, v.y), pack2h(v.z, v.w));
}

// ---------------- main gate kernel (round-13 structure, unchanged) ----------------
__global__ __launch_bounds__(THREADS, 3)
void k_gate(const float* __restrict__ X, float* __restrict__ out, int wbase) {
    extern __shared__ char smem[];
    const int tid  = threadIdx.x;
    const int wid  = tid >> 5;
    const int lane = tid & 31;
    const uint32_t sb = smem_u32(smem);
    const int tokBase = blockIdx.x * TM;

    int* scnt = (int*)(smem + 32768);
    if (tid < NE) scnt[tid] = 0;

    const uint32_t HA = sb;
    const uint32_t HB = sb + 16384u;

    const int xrow = tid >> 2;
    const int xq   = tid & 3;
    const float* xp = X + (size_t)(tokBase + xrow) * HH + xq * 4;
    const char* wp = (const char*)g_wh + (size_t)xrow * (HH * 2) + xq * 16;

    uint32_t xoff[4];
#pragma unroll
    for (int p = 0; p < 4; p++) {
        uint32_t off = (uint32_t)xrow * 128u + (uint32_t)(xq + 4 * p) * 8u;
        xoff[p] = off ^ ((off >> 3) & 0x70);
    }
    uint32_t woff[2];
#pragma unroll
    for (int p = 0; p < 2; p++) {
        uint32_t off = (uint32_t)xrow * 128u + (uint32_t)(xq + 4 * p) * 16u;
        woff[p] = off ^ ((off >> 3) & 0x70);
    }

    const int wm = wid & 1;
    const int wn = wid >> 1;
    const uint32_t xorK  = (uint32_t)(lane & 7);
    const uint32_t kselA = (uint32_t)(lane >> 4);
    const uint32_t kselB = (uint32_t)((lane >> 3) & 1);
    uint32_t rowA[2];
#pragma unroll
    for (int mt = 0; mt < 2; mt++)
        rowA[mt] = (uint32_t)(wm * 32 + mt * 16 + (lane & 15)) * 128u;
    const uint32_t rowB = (uint32_t)(wn * 16 + (lane >> 4) * 8 + (lane & 7)) * 128u;

    float acc[2][2][4];
#pragma unroll
    for (int mt = 0; mt < 2; mt++)
#pragma unroll
        for (int q = 0; q < 2; q++)
#pragma unroll
            for (int e = 0; e < 4; e++) acc[mt][q][e] = 0.0f;

    // prologue: W(0) via cp.async; X(0) into regs
    cp16(HB + woff[0], wp);
    cp16(HB + woff[1], wp + 64);
    CP_COMMIT();
    float4 xv[4];
#pragma unroll
    for (int p = 0; p < 4; p++) xv[p] = *(const float4*)(xp + p * 16);

    for (int t = 0; t < NTILES; t++) {
        const int s = t & 1;
        const uint32_t A = HA + (uint32_t)s * 8192u;
        const uint32_t B = HB + (uint32_t)s * 8192u;

#pragma unroll
        for (int p = 0; p < 4; p++) {
            uint32_t xa = pack2h(xv[p].x, xv[p].y);
            uint32_t xb = pack2h(xv[p].z, xv[p].w);
            asm volatile("st.shared.v2.u32 [%0], {%1,%2};" :: "r"(A + xoff[p]), "r"(xa), "r"(xb));
        }

        if (t + 1 < NTILES) {
            const uint32_t Bn = HB + (uint32_t)((t + 1) & 1) * 8192u;
            cp16(Bn + woff[0], wp + (t + 1) * 128);
            cp16(Bn + woff[1], wp + (t + 1) * 128 + 64);
            CP_COMMIT();
            const int k0 = (t + 1) * KT;
#pragma unroll
            for (int p = 0; p < 4; p++) xv[p] = *(const float4*)(xp + k0 + p * 16);
            CP_WAIT(1);
        } else {
            CP_WAIT(0);
        }

        __syncthreads();

#pragma unroll
        for (int ks = 0; ks < 4; ks++) {
            const uint32_t kA = (uint32_t)(2 * ks) + kselA;
            const uint32_t kB = (uint32_t)(2 * ks) + kselB;
            uint32_t bf[4];
            ldsm4(bf, B + rowB + ((kB ^ xorK) << 4));
            uint32_t af[2][4];
            ldsm4(af[0], A + rowA[0] + ((kA ^ xorK) << 4));
            ldsm4(af[1], A + rowA[1] + ((kA ^ xorK) << 4));
#pragma unroll
            for (int mt = 0; mt < 2; mt++)
#pragma unroll
                for (int q = 0; q < 2; q++)
                    mma16816(acc[mt][q], af[mt], &bf[q * 2]);
        }
    }

    __syncthreads();

    float* Lg = (float*)smem;
    {
        const int g  = lane >> 2;
        const int tg = lane & 3;
#pragma unroll
        for (int mt = 0; mt < 2; mt++)
#pragma unroll
            for (int q = 0; q < 2; q++) {
                int m0 = wm * 32 + mt * 16 + g;
                int c  = wn * 16 + q * 8 + tg * 2;
                Lg[m0 * 66 + c]           = acc[mt][q][0];
                Lg[m0 * 66 + c + 1]       = acc[mt][q][1];
                Lg[(m0 + 8) * 66 + c]     = acc[mt][q][2];
                Lg[(m0 + 8) * 66 + c + 1] = acc[mt][q][3];
            }
    }
    __syncthreads();

    if (tid < TM) {
        float v[64];
#pragma unroll
        for (int e = 0; e < NE; e++) v[e] = Lg[tid * 66 + e];

        float m = -1e30f;
#pragma unroll
        for (int e = 0; e < NE; e++) m = fmaxf(m, v[e]);

        float Z = 0.0f, b1 = -1e30f, b2 = -1e30f, b3 = -1e30f;
        int i1 = 0, i2 = 0;
#pragma unroll
        for (int e = 0; e < NE; e++) {
            float x = v[e];
            float ex = __expf(x - m);
            v[e] = ex;
            Z += ex;
            if (x > b1)      { b3 = b2; b2 = b1; i2 = i1; b1 = x; i1 = e; }
            else if (x > b2) { b3 = b2; b2 = x;  i2 = e; }
            else if (x > b3) { b3 = x; }
        }
        float invZ = 1.0f / Z;
        float s1 = v[i1] * invZ;
        float s2 = v[i2] * invZ;
        float den = s1 + s2 + 1e-20f;

        int gt = tokBase + tid;
        out[gt * 2 + 0] = (float)i1;
        out[gt * 2 + 1] = (float)i2;
        out[wbase + gt * 2 + 0] = s1 / den;
        out[wbase + gt * 2 + 1] = s2 / den;

        if ((b1 - b2 < TAU) || (b2 - b3 < TAU)) {
            int slot = atomicAdd(&g_nfix, 1);
            if (slot < MAXFIX) {
                g_fix[slot] = gt;
                for (int e = 0; e < NE; e++) g_lg[slot * NE + e] = Lg[tid * 66 + e];
            }
        }

        atomicAdd(&scnt[i1], 1);
        atomicAdd(&scnt[i2], 1);

#pragma unroll
        for (int e = 0; e < NE; e++) Lg[tid * 66 + e] = v[e] * invZ;
    }
    __syncthreads();

    if (tid < NE) {
        float ssum = 0.0f;
        for (int r = 0; r < TM; r++) ssum += Lg[r * 66 + tid];
        const int b = tokBase >> 12;
        atomicAdd(&g_ssum[b * NE + tid], ssum);
        int c = scnt[tid];
        if (c) atomicAdd(&g_cnt[b * NE + tid], c);
    }
}

// ---------------- warp-per-token exact fixup + fused aux loss ----------------
__global__ __launch_bounds__(256) void k_fixup(const float* __restrict__ X,
                                               const float* __restrict__ W,
                                               float* __restrict__ out, int wbase,
                                               int aux_idx) {
    __shared__ int   amLast;
    __shared__ float red[NB * NE];
    int n = g_nfix;
    if (n > MAXFIX) n = MAXFIX;
    const int tid  = threadIdx.x;
    const int w    = tid >> 5;
    const int lane = tid & 31;
    const unsigned FULL = 0xffffffffu;

    for (int s = blockIdx.x * 8 + w; s < n; s += gridDim.x * 8) {
        const int gt = g_fix[s];
        float la0 = g_lg[s * NE + lane];
        float la1 = g_lg[s * NE + 32 + lane];

        // ---- approx top-2 value (for candidate threshold) ----
        float t0 = la0, t1 = la1;
        float b1a = warp_max(fmaxf(t0, t1));
        {
            unsigned m0 = __ballot_sync(FULL, t0 == b1a);
            if (m0) { if (lane == __ffs(m0) - 1) t0 = -1e30f; }
            else {
                unsigned m1 = __ballot_sync(FULL, t1 == b1a);
                if (lane == __ffs(m1) - 1) t1 = -1e30f;
            }
        }
        float b2a = warp_max(fmaxf(t0, t1));
        const float thr = b2a - TAU;

        // ---- candidate set: la >= thr ----
        unsigned c0 = __ballot_sync(FULL, la0 >= thr);
        unsigned c1 = __ballot_sync(FULL, la1 >= thr);

        // ---- exact fp32 recompute for each candidate (warp-cooperative) ----
        const float4* xr = (const float4*)(X + (size_t)gt * HH);
        int iter = 0;
        while ((c0 | c1) && iter < 8) {
            iter++;
            int e;
            if (c0) { e = __ffs(c0) - 1; c0 &= c0 - 1; }
            else    { e = 32 + __ffs(c1) - 1; c1 &= c1 - 1; }
            const float4* wr = (const float4*)(W + (size_t)e * HH);
            float a0 = 0.f, a1 = 0.f;
#pragma unroll
            for (int i = 0; i < 16; i += 2) {
                float4 x0 = xr[lane + 32 * i];
                float4 w0 = wr[lane + 32 * i];
                float4 x1 = xr[lane + 32 * (i + 1)];
                float4 w1 = wr[lane + 32 * (i + 1)];
                a0 = fmaf(x0.x, w0.x, a0); a0 = fmaf(x0.y, w0.y, a0);
                a0 = fmaf(x0.z, w0.z, a0); a0 = fmaf(x0.w, w0.w, a0);
                a1 = fmaf(x1.x, w1.x, a1); a1 = fmaf(x1.y, w1.y, a1);
                a1 = fmaf(x1.z, w1.z, a1); a1 = fmaf(x1.w, w1.w, a1);
            }
            float a = warp_sum(a0 + a1);
            if (e < 32) { if (lane == e) la0 = a; }
            else        { if (lane == e - 32) la1 = a; }
        }

        // ---- exact top-2 + softmax over (mixed) logits ----
        float m = warp_max(fmaxf(la0, la1));
        float Z = warp_sum(__expf(la0 - m) + __expf(la1 - m));

        float u0 = la0, u1 = la1;
        float b1 = warp_max(fmaxf(u0, u1));
        int i1;
        {
            unsigned m0 = __ballot_sync(FULL, u0 == b1);
            if (m0) { i1 = __ffs(m0) - 1; if (lane == i1) u0 = -1e30f; }
            else {
                unsigned m1 = __ballot_sync(FULL, u1 == b1);
                i1 = 32 + __ffs(m1) - 1; if (lane == i1 - 32) u1 = -1e30f;
            }
        }
        float b2 = warp_max(fmaxf(u0, u1));
        int i2;
        {
            unsigned m0 = __ballot_sync(FULL, u0 == b2);
            if (m0) i2 = __ffs(m0) - 1;
            else {
                unsigned m1 = __ballot_sync(FULL, u1 == b2);
                i2 = 32 + __ffs(m1) - 1;
            }
        }

        if (lane == 0) {
            float s1 = __expf(b1 - m) / Z;
            float s2 = __expf(b2 - m) / Z;
            float den = s1 + s2 + 1e-20f;

            int o1 = (int)out[gt * 2 + 0];
            int o2 = (int)out[gt * 2 + 1];
            const int b = gt >> 12;
            if (o1 != i1) { atomicAdd(&g_cnt[b * NE + o1], -1); atomicAdd(&g_cnt[b * NE + i1], 1); }
            if (o2 != i2) { atomicAdd(&g_cnt[b * NE + o2], -1); atomicAdd(&g_cnt[b * NE + i2], 1); }

            out[gt * 2 + 0] = (float)i1;
            out[gt * 2 + 1] = (float)i2;
            out[wbase + gt * 2 + 0] = s1 / den;
            out[wbase + gt * 2 + 1] = s2 / den;
        }
    }

    // ---- fused aux loss: last block computes it ----
    __syncthreads();
    __threadfence();
    if (tid == 0) amLast = (atomicAdd(&g_tick, 1) == (int)gridDim.x - 1);
    __syncthreads();
    if (amLast) {
        float v = (float)g_cnt[tid] * ((float)NE / (float)(NS * 2)) * (g_ssum[tid] / (float)NS);
        red[tid] = v;
        g_cnt[tid] = 0;       // reset scratch for next graph replay
        g_ssum[tid] = 0.0f;
        if (tid == 0) { g_tick = 0; g_nfix = 0; }
        __syncthreads();
        for (int s = 128; s > 0; s >>= 1) {
            if (tid < s) red[tid] += red[tid + s];
            __syncthreads();
        }
        if (tid == 0) out[aux_idx] = red[0] / (float)NB * 0.1f;
    }
}

extern "C" void kernel_launch(void* const* d_in, const int* in_sizes, int n_in,
                              void* d_out, int out_size) {
    const float* X = (const float*)d_in[0];   // [4,4096,2048] fp32
    const float* W = (const float*)d_in[1];   // [64,2048] fp32
    float* out = (float*)d_out;
    const int wbase = (out_size - 1) / 2;     // 32768

    cudaFuncSetAttribute(k_gate, cudaFuncAttributeMaxDynamicSharedMemorySize, SMEM_BYTES);

    k_wconv<<<128, 256>>>(W);
    k_gate<<<NT / TM, THREADS, SMEM_BYTES>>>(X, out, wbase);
    k_fixup<<<296, 256>>>(X, W, out, wbase, out_size - 1);
}